// round 2
// baseline (speedup 1.0000x reference)
#include <cuda_runtime.h>
#include <cuda_bf16.h>

#define NB   65536      // batches
#define TPB  64         // threads per block (1 batch per thread)
#define NBLK (NB / TPB) // 1024 blocks

__device__ float g_partials[NBLK];

// clip(log(p), -100, None) -- matches reference _bce clamping.
__device__ __forceinline__ float clogf_(float x) {
    return fmaxf(__logf(x), -100.0f);
}

__device__ __forceinline__ float bce1(float p, float y) {
    float lp = clogf_(p);
    float lm = clogf_(1.0f - p);
    return -(y * lp + (1.0f - y) * lm);
}

__global__ void __launch_bounds__(TPB)
loss_kernel(const float* __restrict__ A, const float* __restrict__ CAT,
            const float* __restrict__ Y, const float* __restrict__ CATL)
{
    const int b = blockIdx.x * TPB + threadIdx.x;

    // Each batch owns 300 floats (3 x 100), read as 75 float4 per array.
    const float4* a4 = reinterpret_cast<const float4*>(A) + (size_t)b * 75;
    const float4* y4 = reinterpret_cast<const float4*>(Y) + (size_t)b * 75;

    float acc[3][3] = {{0.f,0.f,0.f},{0.f,0.f,0.f},{0.f,0.f,0.f}}; // dot(y_t, logp_s - log1mp_s)
    float slog[3]   = {0.f, 0.f, 0.f};                              // sum log1mp_s

    #pragma unroll 5
    for (int k = 0; k < 25; ++k) {
        float4 av[3], yv[3];
        #pragma unroll
        for (int s = 0; s < 3; ++s) av[s] = a4[s * 25 + k];
        #pragma unroll
        for (int t = 0; t < 3; ++t) yv[t] = y4[t * 25 + k];

        float4 df[3];
        #pragma unroll
        for (int s = 0; s < 3; ++s) {
            float lp, lm;
            lp = clogf_(av[s].x); lm = clogf_(1.0f - av[s].x); df[s].x = lp - lm; slog[s] += lm;
            lp = clogf_(av[s].y); lm = clogf_(1.0f - av[s].y); df[s].y = lp - lm; slog[s] += lm;
            lp = clogf_(av[s].z); lm = clogf_(1.0f - av[s].z); df[s].z = lp - lm; slog[s] += lm;
            lp = clogf_(av[s].w); lm = clogf_(1.0f - av[s].w); df[s].w = lp - lm; slog[s] += lm;
        }

        #pragma unroll
        for (int s = 0; s < 3; ++s) {
            #pragma unroll
            for (int t = 0; t < 3; ++t) {
                float a0 = acc[s][t];
                a0 = fmaf(yv[t].x, df[s].x, a0);
                a0 = fmaf(yv[t].y, df[s].y, a0);
                a0 = fmaf(yv[t].z, df[s].z, a0);
                a0 = fmaf(yv[t].w, df[s].w, a0);
                acc[s][t] = a0;
            }
        }
    }

    // C[s][t] = sum_jj bce(a[s], y[t])  (un-normalized by 300)
    float C[3][3];
    #pragma unroll
    for (int s = 0; s < 3; ++s)
        #pragma unroll
        for (int t = 0; t < 3; ++t)
            C[s][t] = -(acc[s][t] + slog[s]);

    // 6 permutations in itertools order; strict < keeps first-min (argmin semantics).
    float best = C[0][0] + C[1][1] + C[2][2];
    int b0 = 0, b1 = 1, b2 = 2;
    {
        float L;
        L = C[0][0] + C[2][1] + C[1][2]; if (L < best) { best = L; b0 = 0; b1 = 2; b2 = 1; }
        L = C[1][0] + C[0][1] + C[2][2]; if (L < best) { best = L; b0 = 1; b1 = 0; b2 = 2; }
        L = C[1][0] + C[2][1] + C[0][2]; if (L < best) { best = L; b0 = 1; b1 = 2; b2 = 0; }
        L = C[2][0] + C[0][1] + C[1][2]; if (L < best) { best = L; b0 = 2; b1 = 0; b2 = 1; }
        L = C[2][0] + C[1][1] + C[0][2]; if (L < best) { best = L; b0 = 2; b1 = 1; b2 = 0; }
    }

    // Category loss with best permutation.
    float c0 = CAT[3 * b + 0], c1 = CAT[3 * b + 1], c2 = CAT[3 * b + 2];
    float l0 = CATL[3 * b + 0], l1 = CATL[3 * b + 1], l2 = CATL[3 * b + 2];
    float p0 = (b0 == 0) ? c0 : ((b0 == 1) ? c1 : c2);
    float p1 = (b1 == 0) ? c0 : ((b1 == 1) ? c1 : c2);
    float p2 = (b2 == 0) ? c0 : ((b2 == 1) ? c1 : c2);
    float catsum = bce1(p0, l0) + bce1(p1, l1) + bce1(p2, l2);

    // total = mean_b(best/300) + mean_{b,t}(cat bce)
    float v = best * (1.0f / 300.0f) * (1.0f / (float)NB)
            + catsum * (1.0f / (3.0f * (float)NB));

    // Deterministic block tree reduction.
    __shared__ float sm[TPB];
    sm[threadIdx.x] = v;
    __syncthreads();
    #pragma unroll
    for (int off = TPB / 2; off > 0; off >>= 1) {
        if (threadIdx.x < off) sm[threadIdx.x] += sm[threadIdx.x + off];
        __syncthreads();
    }
    if (threadIdx.x == 0) g_partials[blockIdx.x] = sm[0];
}

__global__ void __launch_bounds__(256)
reduce_kernel(float* __restrict__ out)
{
    __shared__ float sm[256];
    int t = threadIdx.x;
    float v = 0.0f;
    #pragma unroll
    for (int i = 0; i < NBLK / 256; ++i)
        v += g_partials[t + i * 256];
    sm[t] = v;
    __syncthreads();
    #pragma unroll
    for (int off = 128; off > 0; off >>= 1) {
        if (t < off) sm[t] += sm[t + off];
        __syncthreads();
    }
    if (t == 0) out[0] = sm[0];
}

extern "C" void kernel_launch(void* const* d_in, const int* in_sizes, int n_in,
                              void* d_out, int out_size)
{
    const float* A    = (const float*)d_in[0]; // assignments        (B,3,10,10)
    const float* CAT  = (const float*)d_in[1]; // category           (B,3)
    const float* Y    = (const float*)d_in[2]; // assignments_labels (B,3,10,10)
    const float* CATL = (const float*)d_in[3]; // category_labels    (B,3)

    loss_kernel<<<NBLK, TPB>>>(A, CAT, Y, CATL);
    reduce_kernel<<<1, 256>>>((float*)d_out);
}

// round 3
// speedup vs baseline: 1.1099x; 1.1099x over previous
#include <cuda_runtime.h>
#include <cuda_bf16.h>

#define NB   65536              // batches
#define WPB  8                  // warps per block
#define TPB  (WPB * 32)         // 256 threads
#define BPW  8                  // batches per warp
#define NBLK (NB / (WPB * BPW)) // 1024 blocks

__device__ float g_partials[NBLK];

// clip(log(p), -100, None) -- matches reference _bce clamping.
__device__ __forceinline__ float clogf_(float x) {
    return fmaxf(__logf(x), -100.0f);
}

__device__ __forceinline__ float bce1(float p, float y) {
    float lp = clogf_(p);
    float lm = clogf_(1.0f - p);
    return -(y * lp + (1.0f - y) * lm);
}

__global__ void __launch_bounds__(TPB)
loss_kernel(const float* __restrict__ A, const float* __restrict__ CAT,
            const float* __restrict__ Y, const float* __restrict__ CATL)
{
    const int warp = blockIdx.x * WPB + (threadIdx.x >> 5);
    const int lane = threadIdx.x & 31;
    const bool act = (lane < 25);       // 25 float4 = 100 floats per row

    float vsum = 0.0f;                  // lane 0 accumulates per-warp contribution

    #pragma unroll 2
    for (int i = 0; i < BPW; ++i) {
        const int b = warp * BPW + i;

        // Coalesced row loads: lane l holds elements j = 4l..4l+3 of each row.
        const float4* a4 = reinterpret_cast<const float4*>(A + (size_t)b * 300);
        const float4* y4 = reinterpret_cast<const float4*>(Y + (size_t)b * 300);

        float4 av[3], yv[3];
        #pragma unroll
        for (int s = 0; s < 3; ++s) {
            av[s] = act ? a4[s * 25 + lane] : make_float4(0.f, 0.f, 0.f, 0.f);
            yv[s] = act ? y4[s * 25 + lane] : make_float4(0.f, 0.f, 0.f, 0.f);
        }
        // Inactive lanes (p=0, y=0): lm=log(1)=0, y*df=0 -> contribute exactly 0.

        float slog[3];
        float4 df[3];
        #pragma unroll
        for (int s = 0; s < 3; ++s) {
            float lp, lm, sl = 0.f;
            lp = clogf_(av[s].x); lm = clogf_(1.0f - av[s].x); df[s].x = lp - lm; sl += lm;
            lp = clogf_(av[s].y); lm = clogf_(1.0f - av[s].y); df[s].y = lp - lm; sl += lm;
            lp = clogf_(av[s].z); lm = clogf_(1.0f - av[s].z); df[s].z = lp - lm; sl += lm;
            lp = clogf_(av[s].w); lm = clogf_(1.0f - av[s].w); df[s].w = lp - lm; sl += lm;
            slog[s] = sl;
        }

        float acc[3][3];
        #pragma unroll
        for (int s = 0; s < 3; ++s) {
            #pragma unroll
            for (int t = 0; t < 3; ++t) {
                float a0;
                a0 = yv[t].x * df[s].x;
                a0 = fmaf(yv[t].y, df[s].y, a0);
                a0 = fmaf(yv[t].z, df[s].z, a0);
                a0 = fmaf(yv[t].w, df[s].w, a0);
                acc[s][t] = a0;
            }
        }

        // Warp-reduce the 12 partials (butterfly -> every lane has full sums).
        #pragma unroll
        for (int off = 16; off > 0; off >>= 1) {
            #pragma unroll
            for (int s = 0; s < 3; ++s) {
                acc[s][0] += __shfl_xor_sync(0xffffffffu, acc[s][0], off);
                acc[s][1] += __shfl_xor_sync(0xffffffffu, acc[s][1], off);
                acc[s][2] += __shfl_xor_sync(0xffffffffu, acc[s][2], off);
                slog[s]   += __shfl_xor_sync(0xffffffffu, slog[s],   off);
            }
        }

        // C[s][t] = sum_jj bce(a[s], y[t])  (un-normalized by 300)
        float C[3][3];
        #pragma unroll
        for (int s = 0; s < 3; ++s)
            #pragma unroll
            for (int t = 0; t < 3; ++t)
                C[s][t] = -(acc[s][t] + slog[s]);

        // 6 permutations (itertools order); strict < keeps first-min (argmin).
        float best = C[0][0] + C[1][1] + C[2][2];
        int p0 = 0, p1 = 1, p2 = 2;
        {
            float L;
            L = C[0][0] + C[2][1] + C[1][2]; if (L < best) { best = L; p0 = 0; p1 = 2; p2 = 1; }
            L = C[1][0] + C[0][1] + C[2][2]; if (L < best) { best = L; p0 = 1; p1 = 0; p2 = 2; }
            L = C[1][0] + C[2][1] + C[0][2]; if (L < best) { best = L; p0 = 1; p1 = 2; p2 = 0; }
            L = C[2][0] + C[0][1] + C[1][2]; if (L < best) { best = L; p0 = 2; p1 = 0; p2 = 1; }
            L = C[2][0] + C[1][1] + C[0][2]; if (L < best) { best = L; p0 = 2; p1 = 1; p2 = 0; }
        }

        // Category loss with best permutation (uniform across lanes; lane 0 accumulates).
        float c0 = CAT[3 * b + 0], c1 = CAT[3 * b + 1], c2 = CAT[3 * b + 2];
        float l0 = CATL[3 * b + 0], l1 = CATL[3 * b + 1], l2 = CATL[3 * b + 2];
        float q0 = (p0 == 0) ? c0 : ((p0 == 1) ? c1 : c2);
        float q1 = (p1 == 0) ? c0 : ((p1 == 1) ? c1 : c2);
        float q2 = (p2 == 0) ? c0 : ((p2 == 1) ? c1 : c2);
        float catsum = bce1(q0, l0) + bce1(q1, l1) + bce1(q2, l2);

        if (lane == 0) {
            vsum += best * (1.0f / 300.0f) * (1.0f / (float)NB)
                  + catsum * (1.0f / (3.0f * (float)NB));
        }
    }

    // Deterministic cross-warp reduction within block.
    __shared__ float sm[WPB];
    if (lane == 0) sm[threadIdx.x >> 5] = vsum;
    __syncthreads();
    if (threadIdx.x == 0) {
        float v = 0.0f;
        #pragma unroll
        for (int w = 0; w < WPB; ++w) v += sm[w];
        g_partials[blockIdx.x] = v;
    }
}

__global__ void __launch_bounds__(256)
reduce_kernel(float* __restrict__ out)
{
    __shared__ float sm[256];
    int t = threadIdx.x;
    float v = 0.0f;
    #pragma unroll
    for (int i = 0; i < NBLK / 256; ++i)
        v += g_partials[t + i * 256];
    sm[t] = v;
    __syncthreads();
    #pragma unroll
    for (int off = 128; off > 0; off >>= 1) {
        if (t < off) sm[t] += sm[t + off];
        __syncthreads();
    }
    if (t == 0) out[0] = sm[0];
}

extern "C" void kernel_launch(void* const* d_in, const int* in_sizes, int n_in,
                              void* d_out, int out_size)
{
    const float* A    = (const float*)d_in[0]; // assignments        (B,3,10,10)
    const float* CAT  = (const float*)d_in[1]; // category           (B,3)
    const float* Y    = (const float*)d_in[2]; // assignments_labels (B,3,10,10)
    const float* CATL = (const float*)d_in[3]; // category_labels    (B,3)

    loss_kernel<<<NBLK, TPB>>>(A, CAT, Y, CATL);
    reduce_kernel<<<1, 256>>>((float*)d_out);
}